// round 3
// baseline (speedup 1.0000x reference)
#include <cuda_runtime.h>

// Problem shapes (fixed per reference setup_inputs)
#define BB  2
#define SS  2048
#define HH  4096
#define NHD 32
#define NSL 100
#define DD  64
#define BSR (BB*SS)       // 4096 total (b,s) rows

typedef unsigned long long ull;

// -------- scratch (no allocations allowed) --------
__device__ float g_gate[BSR];
__device__ float g_WqT[HH*DD];    // W_q transposed to [H][D]
__device__ float g_logrel[NSL];
__device__ unsigned g_row_ticket;
__device__ unsigned g_tile_ticket;

// -------- packed f32x2 helpers --------
__device__ __forceinline__ ull pk2(float lo, float hi){
    ull r; asm("mov.b64 %0, {%1, %2};" : "=l"(r) : "f"(lo), "f"(hi)); return r;
}
__device__ __forceinline__ void upk2(ull v, float& lo, float& hi){
    asm("mov.b64 {%0, %1}, %2;" : "=f"(lo), "=f"(hi) : "l"(v));
}
__device__ __forceinline__ void fma2(ull& d, ull a, ull b){
    asm("fma.rn.f32x2 %0, %1, %2, %0;" : "+l"(d) : "l"(a), "l"(b));
}
union F4U { float4 f; ull u[2]; };

// ============================================================
// prep: transpose W_q [D,H] -> WqT [H,D]; log(reliability);
// reset work tickets (runs first every replay -> deterministic)
// ============================================================
__global__ void prep_kernel(const float* __restrict__ Wq,
                            const float* __restrict__ rel)
{
    int idx = blockIdx.x * blockDim.x + threadIdx.x;
    if (idx < HH*DD) {
        int h = idx >> 6, d = idx & 63;
        g_WqT[idx] = Wq[d*HH + h];
    }
    if (idx < NSL) g_logrel[idx] = __logf(rel[idx] + 1e-10f);
    if (idx == 0) { g_row_ticket = 0u; g_tile_ticket = 0u; }
}

// ============================================================
// mega kernel: one wave of 148 CTAs (1 CTA/SM @ 160KB smem).
//   blocks [0, NE)        : entropy+gate over 4096 rows (row tickets)
//   blocks [NE, NE+NF)    : q-proj + scores + softmax + aux GEMM
//                           over 128 row-tiles (tile tickets),
//                           writes UN-GATED aux into out.
// Gate applied later by final_kernel -> the two parts are independent.
// ============================================================
#define NE 56
#define NF 92
#define NGRID (NE+NF)     // 148 == one wave

#define RK   32           // rows per fused tile
#define NTILES (BSR/RK)   // 128
#define KC   256          // k-chunk for q-proj
#define HPAD 260
#define QPAD 68
#define KPAD 68

#define OFF_HID 0
#define OFF_W   (RK*HPAD)                 // 8320
#define OFF_Q   (OFF_W + KC*DD)           // 24704
#define OFF_K   (OFF_Q + RK*QPAD)         // 26880
#define OFF_SC  (OFF_K + NSL*KPAD)        // 33680
#define OFF_AT  (OFF_SC + RK*NSL)         // 36880 (16B aligned)
#define SMEM_FLOATS (OFF_AT + NSL*RK)     // 40080 floats = 160320 B

__global__ __launch_bounds__(256, 1)
void mega_kernel(const float* __restrict__ hidden,
                 const float* __restrict__ paw,
                 const float* __restrict__ keys,
                 const float* __restrict__ vals,
                 const float* __restrict__ w1p,
                 const float* __restrict__ bp,
                 float* __restrict__ out)
{
    extern __shared__ float sm[];
    __shared__ float red[8];
    __shared__ unsigned s_work;
    int t = threadIdx.x;

    if (blockIdx.x < NE) {
        // ======================= ENTROPY PART =======================
        const float w1 = w1p[0], bb = bp[0];
        for (;;) {
            if (t == 0) s_work = atomicAdd(&g_row_ticket, 1u);
            __syncthreads();
            unsigned row = s_work;
            if (row >= BSR) break;

            size_t b = (size_t)(row >> 11);
            size_t s = (size_t)(row & 2047);
            const float* base = paw + ((b*NHD)*SS + s) * (size_t)SS;

            float4 a0 = make_float4(0.f,0.f,0.f,0.f);
            float4 a1 = make_float4(0.f,0.f,0.f,0.f);
            for (int h0 = 0; h0 < NHD; h0 += 8) {
                float4 x0[8], x1[8];
                #pragma unroll
                for (int u = 0; u < 8; ++u) {
                    const float4* p = (const float4*)(base + (size_t)(h0+u)*SS*SS);
                    x0[u] = p[t];
                    x1[u] = p[t + 256];
                }
                #pragma unroll
                for (int u = 0; u < 8; ++u) {
                    a0.x += x0[u].x; a0.y += x0[u].y; a0.z += x0[u].z; a0.w += x0[u].w;
                    a1.x += x1[u].x; a1.y += x1[u].y; a1.z += x1[u].z; a1.w += x1[u].w;
                }
            }
            const float inv = 1.0f / 32.0f;
            float v[8] = {a0.x,a0.y,a0.z,a0.w,a1.x,a1.y,a1.z,a1.w};
            float loc = 0.f;
            #pragma unroll
            for (int i = 0; i < 8; ++i) {
                float a = v[i] * inv;
                loc += a * __logf(a + 1e-10f);
            }
            #pragma unroll
            for (int o = 16; o; o >>= 1) loc += __shfl_xor_sync(0xffffffffu, loc, o);
            if ((t & 31) == 0) red[t >> 5] = loc;
            __syncthreads();
            if (t == 0) {
                float tot = 0.f;
                #pragma unroll
                for (int i = 0; i < 8; ++i) tot += red[i];
                float e = -tot;
                float g = 1.0f / (1.0f + __expf(-(w1*e + bb)));
                if (e < 0.5f)       g = 0.f;
                else if (e > 2.0f)  g = fminf(g, 0.8f);
                g_gate[row] = g;
            }
        }
        return;
    }

    // ========================= FUSED PART =========================
    int r  = t >> 3;       // 0..31
    int d8 = t & 7;        // 0..7

    for (;;) {
        __syncthreads();   // previous tile fully consumed before re-ticket
        if (t == 0) s_work = atomicAdd(&g_tile_ticket, 1u);
        __syncthreads();
        unsigned tile = s_work;
        if (tile >= NTILES) break;
        int row0 = (int)tile * RK;

        // ---------- phase A: q = hidden @ WqT ----------
        ull acc0 = 0, acc1 = 0, acc2 = 0, acc3 = 0;
        for (int k0 = 0; k0 < HH; k0 += KC) {
            #pragma unroll
            for (int i = 0; i < 8; ++i) {
                int idx = t + i*256;                 // 0..2047
                int rr = idx >> 6, c4 = idx & 63;
                float4 x = *(const float4*)(hidden + (size_t)(row0+rr)*HH + k0 + (c4<<2));
                *(float4*)(sm + OFF_HID + rr*HPAD + (c4<<2)) = x;
            }
            const float4* wg = (const float4*)(g_WqT + (size_t)k0*DD);
            #pragma unroll
            for (int i = 0; i < 16; ++i)
                ((float4*)(sm + OFF_W))[t + i*256] = wg[t + i*256];
            __syncthreads();

            const float* hr = sm + OFF_HID + r*HPAD;
            #pragma unroll 4
            for (int h = 0; h < KC; ++h) {
                float a = hr[h];
                ull aa = pk2(a, a);
                F4U w0, w1;
                w0.f = *(const float4*)(sm + OFF_W + h*DD + (d8<<2));
                w1.f = *(const float4*)(sm + OFF_W + h*DD + (d8<<2) + 32);
                fma2(acc0, w0.u[0], aa);
                fma2(acc1, w0.u[1], aa);
                fma2(acc2, w1.u[0], aa);
                fma2(acc3, w1.u[1], aa);
            }
            __syncthreads();
        }
        {
            float x, y;
            float* q = sm + OFF_Q + r*QPAD;
            upk2(acc0, x, y); q[(d8<<2)+0]  = x; q[(d8<<2)+1]  = y;
            upk2(acc1, x, y); q[(d8<<2)+2]  = x; q[(d8<<2)+3]  = y;
            upk2(acc2, x, y); q[(d8<<2)+32] = x; q[(d8<<2)+33] = y;
            upk2(acc3, x, y); q[(d8<<2)+34] = x; q[(d8<<2)+35] = y;
        }
        // keys + logrel into smem
        for (int idx = t; idx < NSL*DD; idx += 256) {
            int n = idx >> 6, d = idx & 63;
            sm[OFF_K + n*KPAD + d] = keys[idx];
        }
        if (t < NSL) sm[OFF_K + t*KPAD + DD] = g_logrel[t];
        __syncthreads();

        // ---------- phase B: scores ----------
        for (int p = t; p < RK*NSL; p += 256) {
            int rr = p / NSL, n = p - rr*NSL;
            const float4* q4 = (const float4*)(sm + OFF_Q + rr*QPAD);
            const float4* k4 = (const float4*)(sm + OFF_K + n*KPAD);
            float acc = 0.f;
            #pragma unroll
            for (int i = 0; i < 16; ++i) {
                float4 a = q4[i], b = k4[i];
                acc += a.x*b.x + a.y*b.y + a.z*b.z + a.w*b.w;
            }
            sm[OFF_SC + rr*NSL + n] = 0.125f*acc + sm[OFF_K + n*KPAD + DD];
        }
        __syncthreads();

        // ---------- phase C: softmax per row (NO gate), pack row-pairs ----------
        {
            int w = t >> 5, lane = t & 31;
            ull* attn2 = (ull*)(sm + OFF_AT);
            #pragma unroll
            for (int j = 0; j < 2; ++j) {
                int rp = w*2 + j;
                int r0 = rp*2, r1 = r0 + 1;
                float e0[4], e1[4];
                float m0 = -1e30f, m1 = -1e30f;
                #pragma unroll
                for (int k = 0; k < 4; ++k) {
                    int n = lane + k*32;
                    float s0 = (n < NSL) ? sm[OFF_SC + r0*NSL + n] : -1e30f;
                    float s1 = (n < NSL) ? sm[OFF_SC + r1*NSL + n] : -1e30f;
                    e0[k] = s0; e1[k] = s1;
                    m0 = fmaxf(m0, s0); m1 = fmaxf(m1, s1);
                }
                #pragma unroll
                for (int o = 16; o; o >>= 1) {
                    m0 = fmaxf(m0, __shfl_xor_sync(0xffffffffu, m0, o));
                    m1 = fmaxf(m1, __shfl_xor_sync(0xffffffffu, m1, o));
                }
                float sum0 = 0.f, sum1 = 0.f;
                #pragma unroll
                for (int k = 0; k < 4; ++k) {
                    int n = lane + k*32;
                    float x0 = (n < NSL) ? __expf(e0[k] - m0) : 0.f;
                    float x1 = (n < NSL) ? __expf(e1[k] - m1) : 0.f;
                    e0[k] = x0; e1[k] = x1;
                    sum0 += x0; sum1 += x1;
                }
                #pragma unroll
                for (int o = 16; o; o >>= 1) {
                    sum0 += __shfl_xor_sync(0xffffffffu, sum0, o);
                    sum1 += __shfl_xor_sync(0xffffffffu, sum1, o);
                }
                float inv0 = 1.0f / sum0;
                float inv1 = 1.0f / sum1;
                #pragma unroll
                for (int k = 0; k < 4; ++k) {
                    int n = lane + k*32;
                    if (n < NSL) attn2[n*16 + rp] = pk2(e0[k]*inv0, e1[k]*inv1);
                }
            }
        }
        __syncthreads();

        // ---------- phase D: aux = attn @ V  (un-gated, stored to out) ----------
        const ull* attn2 = (const ull*)(sm + OFF_AT);
        for (int c0 = 0; c0 < HH; c0 += 512) {
            int cA = c0 + t, cB = cA + 256;
            ull aA[16], aB[16];
            #pragma unroll
            for (int rp = 0; rp < 16; ++rp) { aA[rp] = 0; aB[rp] = 0; }

            // 4-deep prefetch ring on vals to hide L2 latency
            float vA[4], vB[4];
            #pragma unroll
            for (int i = 0; i < 4; ++i) {
                int nn = (i < NSL) ? i : NSL-1;
                vA[i] = vals[(size_t)nn*HH + cA];
                vB[i] = vals[(size_t)nn*HH + cB];
            }
            for (int n = 0; n < NSL; ++n) {
                int np = (n + 4 < NSL) ? n + 4 : NSL-1;
                float nvA = vals[(size_t)np*HH + cA];
                float nvB = vals[(size_t)np*HH + cB];
                int sl = n & 3;
                ull vvA = pk2(vA[sl], vA[sl]), vvB = pk2(vB[sl], vB[sl]);
                const float4* arow = (const float4*)(attn2 + n*16);
                #pragma unroll
                for (int j = 0; j < 8; ++j) {
                    F4U u; u.f = arow[j];            // LDS.128 broadcast
                    fma2(aA[2*j],   u.u[0], vvA);
                    fma2(aA[2*j+1], u.u[1], vvA);
                    fma2(aB[2*j],   u.u[0], vvB);
                    fma2(aB[2*j+1], u.u[1], vvB);
                }
                vA[sl] = nvA; vB[sl] = nvB;
            }
            #pragma unroll
            for (int rp = 0; rp < 16; ++rp) {
                float x, y;
                size_t rb = (size_t)(row0 + rp*2) * HH;
                upk2(aA[rp], x, y); out[rb + cA] = x; out[rb + HH + cA] = y;
                upk2(aB[rp], x, y); out[rb + cB] = x; out[rb + HH + cB] = y;
            }
        }
    }
}

// ============================================================
// final: out = primary + gate[row] * aux   (aux currently in out)
// ============================================================
__global__ __launch_bounds__(256)
void final_kernel(const float* __restrict__ primary,
                  float* __restrict__ out)
{
    const size_t nf4 = (size_t)BSR * (HH/4);      // 4,194,304 float4
    size_t stride = (size_t)gridDim.x * blockDim.x;
    const float4* p4 = (const float4*)primary;
    float4* o4 = (float4*)out;
    for (size_t i = (size_t)blockIdx.x * blockDim.x + threadIdx.x;
         i < nf4; i += stride) {
        int row = (int)(i >> 10);                 // 1024 float4 per row
        float g = g_gate[row];
        float4 a = o4[i];
        float4 p = p4[i];
        float4 r;
        r.x = p.x + g*a.x; r.y = p.y + g*a.y;
        r.z = p.z + g*a.z; r.w = p.w + g*a.w;
        o4[i] = r;
    }
}

// ============================================================
extern "C" void kernel_launch(void* const* d_in, const int* in_sizes, int n_in,
                              void* d_out, int out_size)
{
    const float* hidden  = (const float*)d_in[0];  // [B,S,H]
    const float* primary = (const float*)d_in[1];  // [B,S,H]
    const float* paw     = (const float*)d_in[2];  // [B,NH,S,S]
    const float* rel     = (const float*)d_in[3];  // [NS]
    const float* Wq      = (const float*)d_in[4];  // [D,H]
    const float* keys    = (const float*)d_in[5];  // [NS,D]
    const float* vals    = (const float*)d_in[6];  // [NS,H]
    const float* gw1     = (const float*)d_in[7];  // scalar
    const float* gb      = (const float*)d_in[8];  // scalar
    float* out = (float*)d_out;

    cudaFuncSetAttribute(mega_kernel,
                         cudaFuncAttributeMaxDynamicSharedMemorySize,
                         SMEM_FLOATS * (int)sizeof(float));

    prep_kernel<<<(HH*DD + 255)/256, 256>>>(Wq, rel);
    mega_kernel<<<NGRID, 256, SMEM_FLOATS * sizeof(float)>>>(
        hidden, paw, keys, vals, gw1, gb, out);
    final_kernel<<<2048, 256>>>(primary, out);
}

// round 4
// speedup vs baseline: 1.9734x; 1.9734x over previous
#include <cuda_runtime.h>

// Problem shapes (fixed per reference setup_inputs)
#define BB  2
#define SS  2048
#define HH  4096
#define NHD 32
#define NSL 100
#define NP  128          // slots padded to 128
#define DD  64
#define BSR (BB*SS)      // 4096 rows

typedef unsigned long long ull;

// -------- scratch (no allocations allowed) --------
__device__ float g_gate[BSR];
__device__ float g_KW[HH*NP];       // (W_q^T keys^T)[h][n], pad n>=100 with 0
__device__ float g_logrelp[NP];     // log(rel+eps), pad = -1e30
__device__ float g_attn[BSR*NP];    // softmax(scores), un-gated

// -------- packed f32x2 helpers --------
__device__ __forceinline__ ull pk2(float lo, float hi){
    ull r; asm("mov.b64 %0, {%1, %2};" : "=l"(r) : "f"(lo), "f"(hi)); return r;
}
__device__ __forceinline__ void upk2(ull v, float& lo, float& hi){
    asm("mov.b64 {%0, %1}, %2;" : "=f"(lo), "=f"(hi) : "l"(v));
}
__device__ __forceinline__ void fma2(ull& d, ull a, ull b){
    asm("fma.rn.f32x2 %0, %1, %2, %0;" : "+l"(d) : "l"(a), "l"(b));
}
union F4U { float4 f; ull u[2]; };

// ============================================================
// prep_kw: KW[h][n] = sum_d Wq[d][h] * keys[n][d]; logrelp
// ============================================================
__global__ __launch_bounds__(256)
void prep_kw(const float* __restrict__ Wq,
             const float* __restrict__ keys,
             const float* __restrict__ rel)
{
    __shared__ float sk[NSL*DD];
    int t = threadIdx.x;
    for (int i = t; i < NSL*DD; i += 256) sk[i] = keys[i];
    __syncthreads();

    int h = blockIdx.x*256 + t;          // grid 16 x 256 = 4096
    float wv[DD];
    #pragma unroll
    for (int d = 0; d < DD; ++d) wv[d] = Wq[(size_t)d*HH + h];

    for (int n = 0; n < NP; ++n) {
        float acc = 0.f;
        if (n < NSL) {
            const float* kn = sk + n*DD;
            #pragma unroll
            for (int d = 0; d < DD; ++d) acc += wv[d]*kn[d];
        }
        g_KW[(size_t)h*NP + n] = acc;
    }
    if (blockIdx.x == 0 && t < NP)
        g_logrelp[t] = (t < NSL) ? __logf(rel[t] + 1e-10f) : -1e30f;
}

// ============================================================
// entropy: per (b,s) row, mean over 32 heads, entropy, gate+veto
// (unchanged from R2 — ran near DRAM floor)
// ============================================================
__global__ __launch_bounds__(256)
void entropy_kernel(const float* __restrict__ paw,
                    const float* __restrict__ w1p,
                    const float* __restrict__ bp)
{
    int bs = blockIdx.x;
    int t  = threadIdx.x;
    size_t b = (size_t)(bs >> 11);
    size_t s = (size_t)(bs & 2047);
    const float* base = paw + ((b*NHD)*SS + s) * (size_t)SS;

    float4 a0 = make_float4(0.f,0.f,0.f,0.f);
    float4 a1 = make_float4(0.f,0.f,0.f,0.f);
    for (int h0 = 0; h0 < NHD; h0 += 8) {
        float4 x0[8], x1[8];
        #pragma unroll
        for (int u = 0; u < 8; ++u) {
            const float4* p = (const float4*)(base + (size_t)(h0+u)*SS*SS);
            x0[u] = p[t];
            x1[u] = p[t + 256];
        }
        #pragma unroll
        for (int u = 0; u < 8; ++u) {
            a0.x += x0[u].x; a0.y += x0[u].y; a0.z += x0[u].z; a0.w += x0[u].w;
            a1.x += x1[u].x; a1.y += x1[u].y; a1.z += x1[u].z; a1.w += x1[u].w;
        }
    }
    const float inv = 1.0f / 32.0f;
    float v[8] = {a0.x,a0.y,a0.z,a0.w,a1.x,a1.y,a1.z,a1.w};
    float loc = 0.f;
    #pragma unroll
    for (int i = 0; i < 8; ++i) {
        float a = v[i] * inv;
        loc += a * __logf(a + 1e-10f);
    }
    #pragma unroll
    for (int o = 16; o; o >>= 1) loc += __shfl_xor_sync(0xffffffffu, loc, o);
    __shared__ float red[8];
    if ((t & 31) == 0) red[t >> 5] = loc;
    __syncthreads();
    if (t == 0) {
        float tot = 0.f;
        #pragma unroll
        for (int i = 0; i < 8; ++i) tot += red[i];
        float e = -tot;
        float g = 1.0f / (1.0f + __expf(-(w1p[0]*e + bp[0])));
        if (e < 0.5f)       g = 0.f;
        else if (e > 2.0f)  g = fminf(g, 0.8f);
        g_gate[bs] = g;
    }
}

// ============================================================
// scores: attn = softmax(hidden @ KW / 8 + logrel)
// 128 CTAs x 32 rows. Register double-buffered k-chunks.
// Warp w owns rows w*4..w*4+3; lane owns n = 4*lane..+3.
// hidden stored in smem as duplicated float2 -> direct fma2 operand.
// ============================================================
#define SKC 64
#define NCH (HH/SKC)     // 64 chunks

__global__ __launch_bounds__(256, 1)
void scores_kernel(const float* __restrict__ hidden)
{
    extern __shared__ float smraw[];
    float2* sh = (float2*)smraw;             // [32][SKC] dup pairs, 16KB
    float*  sw = smraw + 32*SKC*2;           // [SKC][NP], 32KB
    int t = threadIdx.x, w = t>>5, lane = t&31;
    int row0 = blockIdx.x*32;

    float4 ph[2], pw[8];
    // prefetch chunk 0
    #pragma unroll
    for (int i = 0; i < 2; ++i) {
        int idx = t + i*256, rr = idx>>4, c4 = idx&15;
        ph[i] = *(const float4*)(hidden + (size_t)(row0+rr)*HH + (c4<<2));
    }
    #pragma unroll
    for (int i = 0; i < 8; ++i) {
        int idx = t + i*256, kk = idx>>5, c4 = idx&31;
        pw[i] = *(const float4*)(g_KW + (size_t)kk*NP + (c4<<2));
    }

    ull a[4][2] = {{0,0},{0,0},{0,0},{0,0}};

    for (int c = 0; c < NCH; ++c) {
        __syncthreads();
        #pragma unroll
        for (int i = 0; i < 2; ++i) {
            int idx = t + i*256, rr = idx>>4, c4 = idx&15;
            float2* d = &sh[rr*SKC + (c4<<2)];
            d[0] = make_float2(ph[i].x, ph[i].x);
            d[1] = make_float2(ph[i].y, ph[i].y);
            d[2] = make_float2(ph[i].z, ph[i].z);
            d[3] = make_float2(ph[i].w, ph[i].w);
        }
        #pragma unroll
        for (int i = 0; i < 8; ++i) {
            int idx = t + i*256, kk = idx>>5, c4 = idx&31;
            *(float4*)(sw + kk*NP + (c4<<2)) = pw[i];
        }
        __syncthreads();

        if (c + 1 < NCH) {
            int k0 = (c+1)*SKC;
            #pragma unroll
            for (int i = 0; i < 2; ++i) {
                int idx = t + i*256, rr = idx>>4, c4 = idx&15;
                ph[i] = *(const float4*)(hidden + (size_t)(row0+rr)*HH + k0 + (c4<<2));
            }
            #pragma unroll
            for (int i = 0; i < 8; ++i) {
                int idx = t + i*256, kk = idx>>5, c4 = idx&31;
                pw[i] = *(const float4*)(g_KW + (size_t)(k0+kk)*NP + (c4<<2));
            }
        }

        const ull* h0 = (const ull*)&sh[(w*4+0)*SKC];
        const ull* h1 = (const ull*)&sh[(w*4+1)*SKC];
        const ull* h2 = (const ull*)&sh[(w*4+2)*SKC];
        const ull* h3 = (const ull*)&sh[(w*4+3)*SKC];
        #pragma unroll 8
        for (int k = 0; k < SKC; ++k) {
            F4U kw; kw.f = *(const float4*)(sw + k*NP + (lane<<2));
            ull hh0 = h0[k], hh1 = h1[k], hh2 = h2[k], hh3 = h3[k];
            fma2(a[0][0], kw.u[0], hh0); fma2(a[0][1], kw.u[1], hh0);
            fma2(a[1][0], kw.u[0], hh1); fma2(a[1][1], kw.u[1], hh1);
            fma2(a[2][0], kw.u[0], hh2); fma2(a[2][1], kw.u[1], hh2);
            fma2(a[3][0], kw.u[0], hh3); fma2(a[3][1], kw.u[1], hh3);
        }
    }

    // softmax per row (pad n>=100 has logrel=-1e30 -> exp=0)
    float4 lr = *(const float4*)(g_logrelp + (lane<<2));
    #pragma unroll
    for (int j = 0; j < 4; ++j) {
        int row = row0 + w*4 + j;
        float s0,s1,s2,s3;
        upk2(a[j][0], s0, s1); upk2(a[j][1], s2, s3);
        s0 = 0.125f*s0 + lr.x; s1 = 0.125f*s1 + lr.y;
        s2 = 0.125f*s2 + lr.z; s3 = 0.125f*s3 + lr.w;
        float m = fmaxf(fmaxf(s0,s1), fmaxf(s2,s3));
        #pragma unroll
        for (int o = 16; o; o >>= 1) m = fmaxf(m, __shfl_xor_sync(0xffffffffu, m, o));
        float e0 = __expf(s0-m), e1 = __expf(s1-m);
        float e2 = __expf(s2-m), e3 = __expf(s3-m);
        float sum = e0+e1+e2+e3;
        #pragma unroll
        for (int o = 16; o; o >>= 1) sum += __shfl_xor_sync(0xffffffffu, sum, o);
        float invs = 1.0f / sum;
        float4 o4 = make_float4(e0*invs, e1*invs, e2*invs, e3*invs);
        *(float4*)(g_attn + (size_t)row*NP + (lane<<2)) = o4;
    }
}
#define SCORES_SMEM (32*SKC*2 + SKC*NP)   // floats: 4096+8192=12288 -> 49152B

// ============================================================
// output: out = primary + gate[row] * (attn @ vals)
// 128 CTAs x 32 rows; gate folded into attn2 at repack.
// ============================================================
__global__ __launch_bounds__(256, 1)
void output_kernel(const float* __restrict__ primary,
                   const float* __restrict__ vals,
                   float* __restrict__ out)
{
    __shared__ ull attn2[NSL*16];   // [n][row-pair], 12.8KB
    __shared__ float sg[32];
    int t = threadIdx.x;
    int row0 = blockIdx.x*32;

    if (t < 32) sg[t] = g_gate[row0 + t];
    __syncthreads();
    for (int idx = t; idx < NSL*16; idx += 256) {
        int n = idx >> 4, rp = idx & 15;
        float a0 = g_attn[(size_t)(row0 + 2*rp  )*NP + n];
        float a1 = g_attn[(size_t)(row0 + 2*rp+1)*NP + n];
        attn2[n*16 + rp] = pk2(a0*sg[2*rp], a1*sg[2*rp+1]);
    }
    __syncthreads();

    for (int c0 = 0; c0 < HH; c0 += 512) {
        int cA = c0 + t, cB = cA + 256;
        ull aA[16], aB[16];
        #pragma unroll
        for (int rp = 0; rp < 16; ++rp) {
            size_t rb = (size_t)(row0 + rp*2) * HH;
            aA[rp] = pk2(primary[rb + cA], primary[rb + HH + cA]);
            aB[rp] = pk2(primary[rb + cB], primary[rb + HH + cB]);
        }
        // 4-deep prefetch ring on vals (L2-resident) to hide latency
        float vA[4], vB[4];
        #pragma unroll
        for (int i = 0; i < 4; ++i) {
            vA[i] = vals[(size_t)i*HH + cA];
            vB[i] = vals[(size_t)i*HH + cB];
        }
        for (int n = 0; n < NSL; ++n) {
            int np = (n + 4 < NSL) ? n + 4 : NSL-1;
            float nvA = vals[(size_t)np*HH + cA];
            float nvB = vals[(size_t)np*HH + cB];
            int sl = n & 3;
            ull vvA = pk2(vA[sl], vA[sl]), vvB = pk2(vB[sl], vB[sl]);
            const float4* arow = (const float4*)(attn2 + n*16);
            #pragma unroll
            for (int j = 0; j < 8; ++j) {
                F4U u; u.f = arow[j];        // broadcast LDS.128
                fma2(aA[2*j],   u.u[0], vvA);
                fma2(aA[2*j+1], u.u[1], vvA);
                fma2(aB[2*j],   u.u[0], vvB);
                fma2(aB[2*j+1], u.u[1], vvB);
            }
            vA[sl] = nvA; vB[sl] = nvB;
        }
        #pragma unroll
        for (int rp = 0; rp < 16; ++rp) {
            float x, y;
            size_t rb = (size_t)(row0 + rp*2) * HH;
            upk2(aA[rp], x, y); out[rb + cA] = x; out[rb + HH + cA] = y;
            upk2(aB[rp], x, y); out[rb + cB] = x; out[rb + HH + cB] = y;
        }
    }
}

// ============================================================
extern "C" void kernel_launch(void* const* d_in, const int* in_sizes, int n_in,
                              void* d_out, int out_size)
{
    const float* hidden  = (const float*)d_in[0];  // [B,S,H]
    const float* primary = (const float*)d_in[1];  // [B,S,H]
    const float* paw     = (const float*)d_in[2];  // [B,NH,S,S]
    const float* rel     = (const float*)d_in[3];  // [NS]
    const float* Wq      = (const float*)d_in[4];  // [D,H]
    const float* keys    = (const float*)d_in[5];  // [NS,D]
    const float* vals    = (const float*)d_in[6];  // [NS,H]
    const float* gw1     = (const float*)d_in[7];  // scalar
    const float* gb      = (const float*)d_in[8];  // scalar
    float* out = (float*)d_out;

    cudaFuncSetAttribute(scores_kernel,
                         cudaFuncAttributeMaxDynamicSharedMemorySize,
                         SCORES_SMEM * (int)sizeof(float));

    prep_kw<<<HH/256, 256>>>(Wq, keys, rel);
    scores_kernel<<<BSR/32, 256, SCORES_SMEM * sizeof(float)>>>(hidden);
    entropy_kernel<<<BSR, 256>>>(paw, gw1, gb);
    output_kernel<<<BSR/32, 256>>>(primary, vals, out);
}

// round 5
// speedup vs baseline: 3.2157x; 1.6296x over previous
#include <cuda_runtime.h>

// Problem shapes (fixed per reference setup_inputs)
#define BB  2
#define SS  2048
#define HH  4096
#define NHD 32
#define NSL 100
#define NP  128          // slots padded to 128
#define DD  64
#define BSR (BB*SS)      // 4096 rows

typedef unsigned long long ull;

// -------- scratch (no allocations allowed) --------
__device__ float g_gate[BSR];
__device__ float g_KW[HH*NP];       // (W_q^T keys^T)[h][n], pad n>=100 with 0
__device__ float g_logrelp[NP];     // log(rel+eps), pad = -1e30
__device__ float g_attn[BSR*NP];    // softmax(scores), un-gated
__device__ unsigned g_row_ticket;

// -------- packed f32x2 helpers --------
__device__ __forceinline__ ull pk2(float lo, float hi){
    ull r; asm("mov.b64 %0, {%1, %2};" : "=l"(r) : "f"(lo), "f"(hi)); return r;
}
__device__ __forceinline__ void upk2(ull v, float& lo, float& hi){
    asm("mov.b64 {%0, %1}, %2;" : "=f"(lo), "=f"(hi) : "l"(v));
}
__device__ __forceinline__ void fma2(ull& d, ull a, ull b){
    asm("fma.rn.f32x2 %0, %1, %2, %0;" : "+l"(d) : "l"(a), "l"(b));
}
union F4U { float4 f; ull u[2]; };

// ============================================================
// prep_kw: KW[h][n] = sum_d Wq[d][h]*keys[n][d]; logrelp; tickets
// ============================================================
__global__ __launch_bounds__(256)
void prep_kw(const float* __restrict__ Wq,
             const float* __restrict__ keys,
             const float* __restrict__ rel)
{
    __shared__ float sk[NSL*DD];
    int t = threadIdx.x;
    for (int i = t; i < NSL*DD; i += 256) sk[i] = keys[i];
    __syncthreads();

    int h = blockIdx.x*256 + t;          // grid 16 x 256 = 4096
    float wv[DD];
    #pragma unroll
    for (int d = 0; d < DD; ++d) wv[d] = Wq[(size_t)d*HH + h];

    for (int n = 0; n < NP; ++n) {
        float acc = 0.f;
        if (n < NSL) {
            const float* kn = sk + n*DD;
            #pragma unroll
            for (int d = 0; d < DD; ++d) acc += wv[d]*kn[d];
        }
        g_KW[(size_t)h*NP + n] = acc;
    }
    if (blockIdx.x == 0 && t < NP)
        g_logrelp[t] = (t < NSL) ? __logf(rel[t] + 1e-10f) : -1e30f;
    if (blockIdx.x == 0 && t == 0) g_row_ticket = 0u;
}

// ============================================================
// mega: grid = 148 (one wave, 1 CTA/SM).
//   blocks [0,128)   : one scores tile (32 rows) each, then join entropy
//   blocks [128,148) : entropy ticket loop from the start
// ============================================================
#define NSCORE 128
#define NGRID  148

#define SKC 64
#define NCH (HH/SKC)     // 64 chunks
#define SCORES_SMEM (32*SKC*2 + SKC*NP)   // floats: 12288 -> 49152B

__device__ __forceinline__ void entropy_loop(const float* __restrict__ paw,
                                             float w1, float bb,
                                             unsigned* s_work, float* red)
{
    int t = threadIdx.x;
    for (;;) {
        __syncthreads();
        if (t == 0) *s_work = atomicAdd(&g_row_ticket, 1u);
        __syncthreads();
        unsigned row = *s_work;
        if (row >= BSR) break;

        size_t b = (size_t)(row >> 11);
        size_t s = (size_t)(row & 2047);
        const float* base = paw + ((b*NHD)*SS + s) * (size_t)SS;

        float4 a0 = make_float4(0.f,0.f,0.f,0.f);
        float4 a1 = make_float4(0.f,0.f,0.f,0.f);
        for (int h0 = 0; h0 < NHD; h0 += 8) {
            float4 x0[8], x1[8];
            #pragma unroll
            for (int u = 0; u < 8; ++u) {
                const float4* p = (const float4*)(base + (size_t)(h0+u)*SS*SS);
                x0[u] = p[t];
                x1[u] = p[t + 256];
            }
            #pragma unroll
            for (int u = 0; u < 8; ++u) {
                a0.x += x0[u].x; a0.y += x0[u].y; a0.z += x0[u].z; a0.w += x0[u].w;
                a1.x += x1[u].x; a1.y += x1[u].y; a1.z += x1[u].z; a1.w += x1[u].w;
            }
        }
        const float inv = 1.0f / 32.0f;
        float v[8] = {a0.x,a0.y,a0.z,a0.w,a1.x,a1.y,a1.z,a1.w};
        float loc = 0.f;
        #pragma unroll
        for (int i = 0; i < 8; ++i) {
            float a = v[i] * inv;
            loc += a * __logf(a + 1e-10f);
        }
        #pragma unroll
        for (int o = 16; o; o >>= 1) loc += __shfl_xor_sync(0xffffffffu, loc, o);
        if ((t & 31) == 0) red[t >> 5] = loc;
        __syncthreads();
        if (t == 0) {
            float tot = 0.f;
            #pragma unroll
            for (int i = 0; i < 8; ++i) tot += red[i];
            float e = -tot;
            float g = 1.0f / (1.0f + __expf(-(w1*e + bb)));
            if (e < 0.5f)       g = 0.f;
            else if (e > 2.0f)  g = fminf(g, 0.8f);
            g_gate[row] = g;
        }
    }
}

__global__ __launch_bounds__(256, 1)
void mega_kernel(const float* __restrict__ hidden,
                 const float* __restrict__ paw,
                 const float* __restrict__ w1p,
                 const float* __restrict__ bp)
{
    extern __shared__ float smraw[];
    __shared__ float red[8];
    __shared__ unsigned s_work;
    int t = threadIdx.x;

    if (blockIdx.x < NSCORE) {
        // =================== one scores tile ===================
        float2* sh = (float2*)smraw;             // [32][SKC] dup pairs, 16KB
        float*  sw = smraw + 32*SKC*2;           // [SKC][NP], 32KB
        int w = t>>5, lane = t&31;
        int row0 = blockIdx.x*32;

        float4 ph[2], pw[8];
        #pragma unroll
        for (int i = 0; i < 2; ++i) {
            int idx = t + i*256, rr = idx>>4, c4 = idx&15;
            ph[i] = *(const float4*)(hidden + (size_t)(row0+rr)*HH + (c4<<2));
        }
        #pragma unroll
        for (int i = 0; i < 8; ++i) {
            int idx = t + i*256, kk = idx>>5, c4 = idx&31;
            pw[i] = *(const float4*)(g_KW + (size_t)kk*NP + (c4<<2));
        }

        ull a[4][2] = {{0,0},{0,0},{0,0},{0,0}};

        for (int c = 0; c < NCH; ++c) {
            __syncthreads();
            #pragma unroll
            for (int i = 0; i < 2; ++i) {
                int idx = t + i*256, rr = idx>>4, c4 = idx&15;
                float2* d = &sh[rr*SKC + (c4<<2)];
                d[0] = make_float2(ph[i].x, ph[i].x);
                d[1] = make_float2(ph[i].y, ph[i].y);
                d[2] = make_float2(ph[i].z, ph[i].z);
                d[3] = make_float2(ph[i].w, ph[i].w);
            }
            #pragma unroll
            for (int i = 0; i < 8; ++i) {
                int idx = t + i*256, kk = idx>>5, c4 = idx&31;
                *(float4*)(sw + kk*NP + (c4<<2)) = pw[i];
            }
            __syncthreads();

            if (c + 1 < NCH) {
                int k0 = (c+1)*SKC;
                #pragma unroll
                for (int i = 0; i < 2; ++i) {
                    int idx = t + i*256, rr = idx>>4, c4 = idx&15;
                    ph[i] = *(const float4*)(hidden + (size_t)(row0+rr)*HH + k0 + (c4<<2));
                }
                #pragma unroll
                for (int i = 0; i < 8; ++i) {
                    int idx = t + i*256, kk = idx>>5, c4 = idx&31;
                    pw[i] = *(const float4*)(g_KW + (size_t)(k0+kk)*NP + (c4<<2));
                }
            }

            const ull* h0 = (const ull*)&sh[(w*4+0)*SKC];
            const ull* h1 = (const ull*)&sh[(w*4+1)*SKC];
            const ull* h2 = (const ull*)&sh[(w*4+2)*SKC];
            const ull* h3 = (const ull*)&sh[(w*4+3)*SKC];
            #pragma unroll 8
            for (int k = 0; k < SKC; ++k) {
                F4U kw; kw.f = *(const float4*)(sw + k*NP + (lane<<2));
                ull hh0 = h0[k], hh1 = h1[k], hh2 = h2[k], hh3 = h3[k];
                fma2(a[0][0], kw.u[0], hh0); fma2(a[0][1], kw.u[1], hh0);
                fma2(a[1][0], kw.u[0], hh1); fma2(a[1][1], kw.u[1], hh1);
                fma2(a[2][0], kw.u[0], hh2); fma2(a[2][1], kw.u[1], hh2);
                fma2(a[3][0], kw.u[0], hh3); fma2(a[3][1], kw.u[1], hh3);
            }
        }

        // softmax per row (pad n>=100 has logrel=-1e30 -> exp=0)
        float4 lr = *(const float4*)(g_logrelp + (lane<<2));
        #pragma unroll
        for (int j = 0; j < 4; ++j) {
            int row = row0 + w*4 + j;
            float s0,s1,s2,s3;
            upk2(a[j][0], s0, s1); upk2(a[j][1], s2, s3);
            s0 = 0.125f*s0 + lr.x; s1 = 0.125f*s1 + lr.y;
            s2 = 0.125f*s2 + lr.z; s3 = 0.125f*s3 + lr.w;
            float m = fmaxf(fmaxf(s0,s1), fmaxf(s2,s3));
            #pragma unroll
            for (int o = 16; o; o >>= 1) m = fmaxf(m, __shfl_xor_sync(0xffffffffu, m, o));
            float e0 = __expf(s0-m), e1 = __expf(s1-m);
            float e2 = __expf(s2-m), e3 = __expf(s3-m);
            float sum = e0+e1+e2+e3;
            #pragma unroll
            for (int o = 16; o; o >>= 1) sum += __shfl_xor_sync(0xffffffffu, sum, o);
            float invs = 1.0f / sum;
            float4 o4 = make_float4(e0*invs, e1*invs, e2*invs, e3*invs);
            *(float4*)(g_attn + (size_t)row*NP + (lane<<2)) = o4;
        }
    }

    // =================== entropy (all CTAs) ===================
    entropy_loop(paw, w1p[0], bp[0], &s_work, red);
}

// ============================================================
// output: out = primary + gate[row]*(attn @ vals)
// grid (128 row-tiles, 8 col-tiles) x 512 thr; 1 col/thread,
// 16 packed row-pair accumulators -> ~60 regs -> 2 CTAs/SM.
// ============================================================
__global__ __launch_bounds__(512, 2)
void output_kernel(const float* __restrict__ primary,
                   const float* __restrict__ vals,
                   float* __restrict__ out)
{
    __shared__ ull attn2[NSL*16];   // [n][row-pair], 12.8KB
    __shared__ float sg[32];
    int t = threadIdx.x;
    int row0 = blockIdx.x*32;
    int c = blockIdx.y*512 + t;

    if (t < 32) sg[t] = g_gate[row0 + t];
    __syncthreads();
    for (int idx = t; idx < NSL*16; idx += 512) {
        int n = idx >> 4, rp = idx & 15;
        float a0 = g_attn[(size_t)(row0 + 2*rp  )*NP + n];
        float a1 = g_attn[(size_t)(row0 + 2*rp+1)*NP + n];
        attn2[n*16 + rp] = pk2(a0*sg[2*rp], a1*sg[2*rp+1]);
    }
    __syncthreads();

    ull acc[16];
    #pragma unroll
    for (int rp = 0; rp < 16; ++rp) {
        size_t rb = (size_t)(row0 + rp*2) * HH;
        acc[rp] = pk2(primary[rb + c], primary[rb + HH + c]);
    }

    // 4-deep prefetch ring on vals (L2-resident)
    float vr[4];
    #pragma unroll
    for (int i = 0; i < 4; ++i) vr[i] = vals[(size_t)i*HH + c];

    for (int n = 0; n < NSL; ++n) {
        int np = (n + 4 < NSL) ? n + 4 : NSL-1;
        float nv = vals[(size_t)np*HH + c];
        int sl = n & 3;
        ull vv = pk2(vr[sl], vr[sl]);
        const float4* arow = (const float4*)(attn2 + n*16);
        #pragma unroll
        for (int j = 0; j < 8; ++j) {
            F4U u; u.f = arow[j];        // broadcast LDS.128
            fma2(acc[2*j],   u.u[0], vv);
            fma2(acc[2*j+1], u.u[1], vv);
        }
        vr[sl] = nv;
    }

    #pragma unroll
    for (int rp = 0; rp < 16; ++rp) {
        float x, y;
        size_t rb = (size_t)(row0 + rp*2) * HH;
        upk2(acc[rp], x, y);
        out[rb + c] = x;
        out[rb + HH + c] = y;
    }
}

// ============================================================
extern "C" void kernel_launch(void* const* d_in, const int* in_sizes, int n_in,
                              void* d_out, int out_size)
{
    const float* hidden  = (const float*)d_in[0];  // [B,S,H]
    const float* primary = (const float*)d_in[1];  // [B,S,H]
    const float* paw     = (const float*)d_in[2];  // [B,NH,S,S]
    const float* rel     = (const float*)d_in[3];  // [NS]
    const float* Wq      = (const float*)d_in[4];  // [D,H]
    const float* keys    = (const float*)d_in[5];  // [NS,D]
    const float* vals    = (const float*)d_in[6];  // [NS,H]
    const float* gw1     = (const float*)d_in[7];  // scalar
    const float* gb      = (const float*)d_in[8];  // scalar
    float* out = (float*)d_out;

    cudaFuncSetAttribute(mega_kernel,
                         cudaFuncAttributeMaxDynamicSharedMemorySize,
                         SCORES_SMEM * (int)sizeof(float));

    prep_kw<<<HH/256, 256>>>(Wq, keys, rel);
    mega_kernel<<<NGRID, 256, SCORES_SMEM * sizeof(float)>>>(hidden, paw, gw1, gb);
    output_kernel<<<dim3(BSR/32, 8), 512>>>(primary, vals, out);
}

// round 6
// speedup vs baseline: 4.3470x; 1.3518x over previous
#include <cuda_runtime.h>

// Problem shapes (fixed per reference setup_inputs)
#define BB  2
#define SS  2048
#define HH  4096
#define NHD 32
#define NSL 100
#define NP  128          // slots padded to 128
#define DD  64
#define BSR (BB*SS)      // 4096 rows

typedef unsigned long long ull;

// -------- scratch (no allocations allowed) --------
__device__ float g_gate[BSR];
__device__ float g_KW[HH*NP];       // (W_q^T keys^T)[h][n], pad n>=100 with 0
__device__ float g_logrelp[NP];     // log(rel+eps), pad = -1e30
__device__ float g_attn[BSR*NP];    // softmax(scores), un-gated
__device__ unsigned g_row_ticket;

// -------- packed f32x2 helpers --------
__device__ __forceinline__ ull pk2(float lo, float hi){
    ull r; asm("mov.b64 %0, {%1, %2};" : "=l"(r) : "f"(lo), "f"(hi)); return r;
}
__device__ __forceinline__ void upk2(ull v, float& lo, float& hi){
    asm("mov.b64 {%0, %1}, %2;" : "=f"(lo), "=f"(hi) : "l"(v));
}
__device__ __forceinline__ void fma2(ull& d, ull a, ull b){
    asm("fma.rn.f32x2 %0, %1, %2, %0;" : "+l"(d) : "l"(a), "l"(b));
}
union F4U { float4 f; ull u[2]; };

// ============================================================
// prep_kw: KW[h][n] = sum_d Wq[d][h]*keys[n][d]
// grid (16, 4): block y owns n in [32y, 32y+32) -> 64 CTAs
// ============================================================
__global__ __launch_bounds__(256)
void prep_kw(const float* __restrict__ Wq,
             const float* __restrict__ keys,
             const float* __restrict__ rel)
{
    __shared__ float sk[32*DD];
    int t = threadIdx.x;
    int n0 = blockIdx.y * 32;
    for (int i = t; i < 32*DD; i += 256) {
        int n = i >> 6, d = i & 63;
        sk[i] = ((n0 + n) < NSL) ? keys[(n0+n)*DD + d] : 0.f;
    }
    __syncthreads();

    int h = blockIdx.x*256 + t;
    float wv[DD];
    #pragma unroll
    for (int d = 0; d < DD; ++d) wv[d] = Wq[(size_t)d*HH + h];

    #pragma unroll 4
    for (int n = 0; n < 32; ++n) {
        float acc = 0.f;
        const float* kn = sk + n*DD;
        #pragma unroll
        for (int d = 0; d < DD; ++d) acc += wv[d]*kn[d];
        g_KW[(size_t)h*NP + n0 + n] = acc;
    }
    if (blockIdx.x == 0 && blockIdx.y == 0 && t < NP)
        g_logrelp[t] = (t < NSL) ? __logf(rel[t] + 1e-10f) : -1e30f;
    if (blockIdx.x == 0 && blockIdx.y == 0 && t == 0) g_row_ticket = 0u;
}

// ============================================================
// mega: grid = 296 (2 CTAs/SM).
//   blocks [0,148)    : entropy ticket loop from t=0 (1 per SM,
//                       keeps DRAM saturated throughout)
//   blocks [148,276)  : one scores tile (fma-bound, co-resident
//                       on same SMs), then join entropy
//   blocks [276,296)  : entropy
// ============================================================
#define NENT  148
#define NSCORE 128
#define NGRID (NENT + NSCORE + 20)   // 296

#define SKC 64
#define NCH (HH/SKC)     // 64 chunks
#define SCORES_SMEM (32*SKC*2 + SKC*NP)   // floats: 12288 -> 49152B

__device__ __forceinline__ void entropy_loop(const float* __restrict__ paw,
                                             float w1, float bb,
                                             unsigned* s_work, float* red)
{
    int t = threadIdx.x;
    for (;;) {
        __syncthreads();
        if (t == 0) *s_work = atomicAdd(&g_row_ticket, 1u);
        __syncthreads();
        unsigned row = *s_work;
        if (row >= BSR) break;

        size_t b = (size_t)(row >> 11);
        size_t s = (size_t)(row & 2047);
        const float* base = paw + ((b*NHD)*SS + s) * (size_t)SS;

        float4 a0 = make_float4(0.f,0.f,0.f,0.f);
        float4 a1 = make_float4(0.f,0.f,0.f,0.f);
        for (int h0 = 0; h0 < NHD; h0 += 8) {
            float4 x0[8], x1[8];
            #pragma unroll
            for (int u = 0; u < 8; ++u) {
                const float4* p = (const float4*)(base + (size_t)(h0+u)*SS*SS);
                x0[u] = p[t];
                x1[u] = p[t + 256];
            }
            #pragma unroll
            for (int u = 0; u < 8; ++u) {
                a0.x += x0[u].x; a0.y += x0[u].y; a0.z += x0[u].z; a0.w += x0[u].w;
                a1.x += x1[u].x; a1.y += x1[u].y; a1.z += x1[u].z; a1.w += x1[u].w;
            }
        }
        const float inv = 1.0f / 32.0f;
        float v[8] = {a0.x,a0.y,a0.z,a0.w,a1.x,a1.y,a1.z,a1.w};
        float loc = 0.f;
        #pragma unroll
        for (int i = 0; i < 8; ++i) {
            float a = v[i] * inv;
            loc += a * __logf(a + 1e-10f);
        }
        #pragma unroll
        for (int o = 16; o; o >>= 1) loc += __shfl_xor_sync(0xffffffffu, loc, o);
        if ((t & 31) == 0) red[t >> 5] = loc;
        __syncthreads();
        if (t == 0) {
            float tot = 0.f;
            #pragma unroll
            for (int i = 0; i < 8; ++i) tot += red[i];
            float e = -tot;
            float g = 1.0f / (1.0f + __expf(-(w1*e + bb)));
            if (e < 0.5f)       g = 0.f;
            else if (e > 2.0f)  g = fminf(g, 0.8f);
            g_gate[row] = g;
        }
    }
}

__global__ __launch_bounds__(256, 2)
void mega_kernel(const float* __restrict__ hidden,
                 const float* __restrict__ paw,
                 const float* __restrict__ w1p,
                 const float* __restrict__ bp)
{
    extern __shared__ float smraw[];
    __shared__ float red[8];
    __shared__ unsigned s_work;
    int t = threadIdx.x;
    int bid = blockIdx.x;

    if (bid >= NENT && bid < NENT + NSCORE) {
        // =================== one scores tile ===================
        float2* sh = (float2*)smraw;             // [32][SKC] dup pairs, 16KB
        float*  sw = smraw + 32*SKC*2;           // [SKC][NP], 32KB
        int w = t>>5, lane = t&31;
        int row0 = (bid - NENT)*32;

        float4 ph[2], pw[8];
        #pragma unroll
        for (int i = 0; i < 2; ++i) {
            int idx = t + i*256, rr = idx>>4, c4 = idx&15;
            ph[i] = *(const float4*)(hidden + (size_t)(row0+rr)*HH + (c4<<2));
        }
        #pragma unroll
        for (int i = 0; i < 8; ++i) {
            int idx = t + i*256, kk = idx>>5, c4 = idx&31;
            pw[i] = *(const float4*)(g_KW + (size_t)kk*NP + (c4<<2));
        }

        ull a[4][2] = {{0,0},{0,0},{0,0},{0,0}};

        for (int c = 0; c < NCH; ++c) {
            __syncthreads();
            #pragma unroll
            for (int i = 0; i < 2; ++i) {
                int idx = t + i*256, rr = idx>>4, c4 = idx&15;
                float2* d = &sh[rr*SKC + (c4<<2)];
                d[0] = make_float2(ph[i].x, ph[i].x);
                d[1] = make_float2(ph[i].y, ph[i].y);
                d[2] = make_float2(ph[i].z, ph[i].z);
                d[3] = make_float2(ph[i].w, ph[i].w);
            }
            #pragma unroll
            for (int i = 0; i < 8; ++i) {
                int idx = t + i*256, kk = idx>>5, c4 = idx&31;
                *(float4*)(sw + kk*NP + (c4<<2)) = pw[i];
            }
            __syncthreads();

            if (c + 1 < NCH) {
                int k0 = (c+1)*SKC;
                #pragma unroll
                for (int i = 0; i < 2; ++i) {
                    int idx = t + i*256, rr = idx>>4, c4 = idx&15;
                    ph[i] = *(const float4*)(hidden + (size_t)(row0+rr)*HH + k0 + (c4<<2));
                }
                #pragma unroll
                for (int i = 0; i < 8; ++i) {
                    int idx = t + i*256, kk = idx>>5, c4 = idx&31;
                    pw[i] = *(const float4*)(g_KW + (size_t)(k0+kk)*NP + (c4<<2));
                }
            }

            const ull* h0 = (const ull*)&sh[(w*4+0)*SKC];
            const ull* h1 = (const ull*)&sh[(w*4+1)*SKC];
            const ull* h2 = (const ull*)&sh[(w*4+2)*SKC];
            const ull* h3 = (const ull*)&sh[(w*4+3)*SKC];
            #pragma unroll 8
            for (int k = 0; k < SKC; ++k) {
                F4U kw; kw.f = *(const float4*)(sw + k*NP + (lane<<2));
                ull hh0 = h0[k], hh1 = h1[k], hh2 = h2[k], hh3 = h3[k];
                fma2(a[0][0], kw.u[0], hh0); fma2(a[0][1], kw.u[1], hh0);
                fma2(a[1][0], kw.u[0], hh1); fma2(a[1][1], kw.u[1], hh1);
                fma2(a[2][0], kw.u[0], hh2); fma2(a[2][1], kw.u[1], hh2);
                fma2(a[3][0], kw.u[0], hh3); fma2(a[3][1], kw.u[1], hh3);
            }
        }

        // softmax per row (pad n>=100 has logrel=-1e30 -> exp=0)
        float4 lr = *(const float4*)(g_logrelp + (lane<<2));
        #pragma unroll
        for (int j = 0; j < 4; ++j) {
            int row = row0 + w*4 + j;
            float s0,s1,s2,s3;
            upk2(a[j][0], s0, s1); upk2(a[j][1], s2, s3);
            s0 = 0.125f*s0 + lr.x; s1 = 0.125f*s1 + lr.y;
            s2 = 0.125f*s2 + lr.z; s3 = 0.125f*s3 + lr.w;
            float m = fmaxf(fmaxf(s0,s1), fmaxf(s2,s3));
            #pragma unroll
            for (int o = 16; o; o >>= 1) m = fmaxf(m, __shfl_xor_sync(0xffffffffu, m, o));
            float e0 = __expf(s0-m), e1 = __expf(s1-m);
            float e2 = __expf(s2-m), e3 = __expf(s3-m);
            float sum = e0+e1+e2+e3;
            #pragma unroll
            for (int o = 16; o; o >>= 1) sum += __shfl_xor_sync(0xffffffffu, sum, o);
            float invs = 1.0f / sum;
            float4 o4 = make_float4(e0*invs, e1*invs, e2*invs, e3*invs);
            *(float4*)(g_attn + (size_t)row*NP + (lane<<2)) = o4;
        }
    }

    // =================== entropy (all CTAs) ===================
    entropy_loop(paw, w1p[0], bp[0], &s_work, red);
}

// ============================================================
// output: out = primary + gate[row]*(attn @ vals)
// grid (128 row-tiles, 8 col-tiles) x 512 thr; 1 col/thread,
// 16 packed row-pair accumulators; 2 CTAs/SM.
// ============================================================
__global__ __launch_bounds__(512, 2)
void output_kernel(const float* __restrict__ primary,
                   const float* __restrict__ vals,
                   float* __restrict__ out)
{
    __shared__ ull attn2[NSL*16];   // [n][row-pair], 12.8KB
    __shared__ float sg[32];
    int t = threadIdx.x;
    int row0 = blockIdx.x*32;
    int c = blockIdx.y*512 + t;

    if (t < 32) sg[t] = g_gate[row0 + t];
    __syncthreads();
    for (int idx = t; idx < NSL*16; idx += 512) {
        int n = idx >> 4, rp = idx & 15;
        float a0 = g_attn[(size_t)(row0 + 2*rp  )*NP + n];
        float a1 = g_attn[(size_t)(row0 + 2*rp+1)*NP + n];
        attn2[n*16 + rp] = pk2(a0*sg[2*rp], a1*sg[2*rp+1]);
    }
    __syncthreads();

    ull acc[16];
    #pragma unroll
    for (int rp = 0; rp < 16; ++rp) {
        size_t rb = (size_t)(row0 + rp*2) * HH;
        acc[rp] = pk2(primary[rb + c], primary[rb + HH + c]);
    }

    // 4-deep prefetch ring on vals (L2-resident)
    float vr[4];
    #pragma unroll
    for (int i = 0; i < 4; ++i) vr[i] = vals[(size_t)i*HH + c];

    for (int n = 0; n < NSL; ++n) {
        int np = (n + 4 < NSL) ? n + 4 : NSL-1;
        float nv = vals[(size_t)np*HH + c];
        int sl = n & 3;
        ull vv = pk2(vr[sl], vr[sl]);
        const float4* arow = (const float4*)(attn2 + n*16);
        #pragma unroll
        for (int j = 0; j < 8; ++j) {
            F4U u; u.f = arow[j];        // broadcast LDS.128
            fma2(acc[2*j],   u.u[0], vv);
            fma2(acc[2*j+1], u.u[1], vv);
        }
        vr[sl] = nv;
    }

    #pragma unroll
    for (int rp = 0; rp < 16; ++rp) {
        float x, y;
        size_t rb = (size_t)(row0 + rp*2) * HH;
        upk2(acc[rp], x, y);
        out[rb + c] = x;
        out[rb + HH + c] = y;
    }
}

// ============================================================
extern "C" void kernel_launch(void* const* d_in, const int* in_sizes, int n_in,
                              void* d_out, int out_size)
{
    const float* hidden  = (const float*)d_in[0];  // [B,S,H]
    const float* primary = (const float*)d_in[1];  // [B,S,H]
    const float* paw     = (const float*)d_in[2];  // [B,NH,S,S]
    const float* rel     = (const float*)d_in[3];  // [NS]
    const float* Wq      = (const float*)d_in[4];  // [D,H]
    const float* keys    = (const float*)d_in[5];  // [NS,D]
    const float* vals    = (const float*)d_in[6];  // [NS,H]
    const float* gw1     = (const float*)d_in[7];  // scalar
    const float* gb      = (const float*)d_in[8];  // scalar
    float* out = (float*)d_out;

    cudaFuncSetAttribute(mega_kernel,
                         cudaFuncAttributeMaxDynamicSharedMemorySize,
                         SCORES_SMEM * (int)sizeof(float));

    prep_kw<<<dim3(HH/256, 4), 256>>>(Wq, keys, rel);
    mega_kernel<<<NGRID, 256, SCORES_SMEM * sizeof(float)>>>(hidden, paw, gw1, gb);
    output_kernel<<<dim3(BSR/32, 8), 512>>>(primary, vals, out);
}